// round 8
// baseline (speedup 1.0000x reference)
#include <cuda_runtime.h>
#include <cstdint>

// exp(X) for batched 32x32 symmetric fp32: scaling-and-squaring + degree-8
// Paterson-Stockmeyer Taylor with relaxed radius (theta=1.35 -> one fewer
// squaring; truncation ~1e-5, x8 amplification ~1e-4 << 1e-3 budget).
// TWO matrices per warp (half-warp h owns matrix h, lane owns columns jj,
// jj+16). mm: A-rows broadcast from smem (LDS.128, half-warps bank-disjoint),
// B-columns in registers, full 64-reg f32x2 accumulator (R2-proven form).
// NO launch_bounds cap (caps proven to spill: R3/R5/R6/R7).
// Two smem buffers:  A: X -> B0 -> P(squaring chain)   E: Xs -> Z
// Folding (verified): B1 = 168*B2 - 0.075*I + B0/120.

#define STRIDE 36               // floats per smem row
#define ROWB   144              // bytes per smem row
#define MOFF   1168             // matrix-1 word offset (+16-bank shift)
#define BUFF   2320             // floats per buffer (2 matrices)

typedef unsigned long long u64;

static __device__ __forceinline__ u64 pk2(float v) {
    u64 r; asm("mov.b64 %0, {%1, %1};" : "=l"(r) : "f"(v)); return r;
}
static __device__ __forceinline__ void upk2(float& lo, float& hi, u64 v) {
    asm("mov.b64 {%0, %1}, %2;" : "=f"(lo), "=f"(hi) : "l"(v));
}
static __device__ __forceinline__ void fma2(u64& d, u64 a, u64 b) {
    asm("fma.rn.f32x2 %0, %1, %2, %0;" : "+l"(d) : "l"(a), "l"(b));
}
static __device__ __forceinline__ u64 mul2(u64 a, u64 b) {
    u64 d; asm("mul.rn.f32x2 %0, %1, %2;" : "=l"(d) : "l"(a), "l"(b)); return d;
}
static __device__ __forceinline__ float ldsf(uint32_t a) {
    float f; asm volatile("ld.shared.f32 %0, [%1];" : "=f"(f) : "r"(a)); return f;
}
static __device__ __forceinline__ void stsf(uint32_t a, float f) {
    asm volatile("st.shared.f32 [%0], %1;" :: "r"(a), "f"(f));
}

// C(:,c0|c1) = A * b; full 32-row accumulator (R2 form).
static __device__ __forceinline__ void mm2(uint32_t aBase, const float* b0,
                                           const float* b1,
                                           u64 acc0[16], u64 acc1[16]) {
    {   // k = 0 peeled: mul (no zero-init MOVs)
        u64 bb0 = pk2(b0[0]), bb1 = pk2(b1[0]);
#pragma unroll
        for (int q = 0; q < 8; ++q) {
            u64 a0, a1;
            asm volatile("ld.shared.v2.u64 {%0, %1}, [%2];"
                         : "=l"(a0), "=l"(a1) : "r"(aBase + (uint32_t)(q * 16)));
            acc0[2 * q]     = mul2(a0, bb0);
            acc0[2 * q + 1] = mul2(a1, bb0);
            acc1[2 * q]     = mul2(a0, bb1);
            acc1[2 * q + 1] = mul2(a1, bb1);
        }
    }
#pragma unroll
    for (int k = 1; k < 32; ++k) {
        u64 bb0 = pk2(b0[k]), bb1 = pk2(b1[k]);
        const uint32_t ra = aBase + (uint32_t)(k * ROWB);
#pragma unroll
        for (int q = 0; q < 8; ++q) {
            u64 a0, a1;
            asm volatile("ld.shared.v2.u64 {%0, %1}, [%2];"
                         : "=l"(a0), "=l"(a1) : "r"(ra + (uint32_t)(q * 16)));
            fma2(acc0[2 * q],     a0, bb0);
            fma2(acc0[2 * q + 1], a1, bb0);
            fma2(acc1[2 * q],     a0, bb1);
            fma2(acc1[2 * q + 1], a1, bb1);
        }
    }
}

__global__ void __launch_bounds__(32)
ExpEig_52553219834314_kernel(const float* __restrict__ in,
                             float* __restrict__ out, int B) {
    __shared__ __align__(16) float smem[2 * BUFF];

    const int lane = threadIdx.x;
    const int h = lane >> 4, jj = lane & 15;
    int mat = blockIdx.x * 2 + h;
    const bool alive = (mat < B);
    if (!alive) mat = B - 1;
    const int c0 = jj, c1 = jj + 16;

    const uint32_t aA = (uint32_t)__cvta_generic_to_shared(smem)
                      + (uint32_t)(h * MOFF * 4);
    const uint32_t aE = aA + (uint32_t)(BUFF * 4);
    const uint32_t Ac0 = aA + (uint32_t)(c0 * 4), Ac1 = aA + (uint32_t)(c1 * 4);
    const uint32_t Ec0 = aE + (uint32_t)(c0 * 4), Ec1 = aE + (uint32_t)(c1 * 4);

    // Load X columns -> regs, mirror into A.
    float b0[32], b1[32];
    {
        const float* src = in + (size_t)mat * 1024;
#pragma unroll
        for (int i = 0; i < 32; ++i) {
            b0[i] = src[i * 32 + c0];
            b1[i] = src[i * 32 + c1];
        }
#pragma unroll
        for (int i = 0; i < 32; ++i) {
            stsf(Ac0 + (uint32_t)(i * ROWB), b0[i]);
            stsf(Ac1 + (uint32_t)(i * ROWB), b1[i]);
        }
    }
    __syncwarp();

    u64 acc0[16], acc1[16];

    // ---- stage 0: X2 = X * X
    mm2(aA, b0, b1, acc0, acc1);

    // Spectral bound: ||X||_2 <= sqrt(min(||X2||_1, ||X2||_F)).
    float rs, fb = 0.f;
    {
        float sa = 0.f, sb = 0.f;
#pragma unroll
        for (int p = 0; p < 16; ++p) {
            float t0, t1, u0, u1;
            upk2(t0, t1, acc0[p]); upk2(u0, u1, acc1[p]);
            sa += fabsf(t0) + fabsf(t1);
            sb += fabsf(u0) + fabsf(u1);
            fb += t0 * t0 + t1 * t1 + u0 * u0 + u1 * u1;
        }
        rs = fmaxf(sa, sb);
    }
#pragma unroll
    for (int off = 8; off > 0; off >>= 1) {
        rs = fmaxf(rs, __shfl_xor_sync(0xffffffffu, rs, off));
        fb += __shfl_xor_sync(0xffffffffu, fb, off);
    }
    float bnd = sqrtf(fminf(rs, sqrtf(fb)));
    bnd = fmaxf(bnd, __shfl_xor_sync(0xffffffffu, bnd, 16));
    // Relaxed radius: scale so ||Xs|| <= 1.35 (one fewer squaring than theta=1).
    int e = 0; (void)frexpf(bnd * (1.f / 1.35f), &e);   // bnd/1.35 <= 2^e
    const int kk = e < 0 ? 0 : (e > 24 ? 24 : e);
    const int total = 4 + kk;
    const float s1f = exp2f(-(float)kk), s2f = s1f * s1f;

    // E := Xs = s1*X (lane-private from b);  b := X2s = s2*acc.
#pragma unroll
    for (int i = 0; i < 32; ++i) {
        stsf(Ec0 + (uint32_t)(i * ROWB), s1f * b0[i]);
        stsf(Ec1 + (uint32_t)(i * ROWB), s1f * b1[i]);
    }
#pragma unroll
    for (int p = 0; p < 16; ++p) {
        upk2(b0[2 * p], b0[2 * p + 1], acc0[p]);
        upk2(b1[2 * p], b1[2 * p + 1], acc1[p]);
        b0[2 * p] *= s2f; b0[2 * p + 1] *= s2f;
        b1[2 * p] *= s2f; b1[2 * p + 1] *= s2f;
    }
    __syncwarp();   // Xs visible warp-wide

    // ---- stage 1: Z = Xs * X2s   (A-op = E = Xs, B-op = X2s regs)
    mm2(aE, b0, b1, acc0, acc1);
    __syncwarp();   // cross-lane reads of E (Xs) complete before overwrite
    // A := B0 = I + Xs + X2s/2 ; b := B2 = I/720 + Xs/5040 + X2s/40320 ; E := Z
#pragma unroll
    for (int p = 0; p < 16; ++p) {
        const int i0 = 2 * p, i1 = 2 * p + 1;
        float z00, z01, z10, z11;
        upk2(z00, z01, acc0[p]); upk2(z10, z11, acc1[p]);
        {
            float xs = ldsf(Ec0 + (uint32_t)(i0 * ROWB));
            float kr = (i0 == c0) ? 1.f : 0.f;
            stsf(Ac0 + (uint32_t)(i0 * ROWB), kr + xs + 0.5f * b0[i0]);
            b0[i0] = kr * (1.f / 720.f) + xs * (1.f / 5040.f) + b0[i0] * (1.f / 40320.f);
            stsf(Ec0 + (uint32_t)(i0 * ROWB), z00);
        }
        {
            float xs = ldsf(Ec0 + (uint32_t)(i1 * ROWB));
            float kr = (i1 == c0) ? 1.f : 0.f;
            stsf(Ac0 + (uint32_t)(i1 * ROWB), kr + xs + 0.5f * b0[i1]);
            b0[i1] = kr * (1.f / 720.f) + xs * (1.f / 5040.f) + b0[i1] * (1.f / 40320.f);
            stsf(Ec0 + (uint32_t)(i1 * ROWB), z01);
        }
        {
            float xs = ldsf(Ec1 + (uint32_t)(i0 * ROWB));
            float kr = (i0 == c1) ? 1.f : 0.f;
            stsf(Ac1 + (uint32_t)(i0 * ROWB), kr + xs + 0.5f * b1[i0]);
            b1[i0] = kr * (1.f / 720.f) + xs * (1.f / 5040.f) + b1[i0] * (1.f / 40320.f);
            stsf(Ec1 + (uint32_t)(i0 * ROWB), z10);
        }
        {
            float xs = ldsf(Ec1 + (uint32_t)(i1 * ROWB));
            float kr = (i1 == c1) ? 1.f : 0.f;
            stsf(Ac1 + (uint32_t)(i1 * ROWB), kr + xs + 0.5f * b1[i1]);
            b1[i1] = kr * (1.f / 720.f) + xs * (1.f / 5040.f) + b1[i1] * (1.f / 40320.f);
            stsf(Ec1 + (uint32_t)(i1 * ROWB), z11);
        }
    }
    __syncwarp();   // Z visible warp-wide

    // ---- stage 2: U = Z * B2   (A-op = E = Z, B-op = B2 regs; commute OK)
    mm2(aE, b0, b1, acc0, acc1);
    // b := V = U + 168*B2 - 0.075*I + B0/120   (B0 from A, lane-private)
#pragma unroll
    for (int p = 0; p < 16; ++p) {
        const int i0 = 2 * p, i1 = 2 * p + 1;
        float u00, u01, u10, u11;
        upk2(u00, u01, acc0[p]); upk2(u10, u11, acc1[p]);
        b0[i0] = u00 + 168.f * b0[i0] - 0.075f * ((i0 == c0) ? 1.f : 0.f)
               + ldsf(Ac0 + (uint32_t)(i0 * ROWB)) * (1.f / 120.f);
        b0[i1] = u01 + 168.f * b0[i1] - 0.075f * ((i1 == c0) ? 1.f : 0.f)
               + ldsf(Ac0 + (uint32_t)(i1 * ROWB)) * (1.f / 120.f);
        b1[i0] = u10 + 168.f * b1[i0] - 0.075f * ((i0 == c1) ? 1.f : 0.f)
               + ldsf(Ac1 + (uint32_t)(i0 * ROWB)) * (1.f / 120.f);
        b1[i1] = u11 + 168.f * b1[i1] - 0.075f * ((i1 == c1) ? 1.f : 0.f)
               + ldsf(Ac1 + (uint32_t)(i1 * ROWB)) * (1.f / 120.f);
    }
    // No sync: E untouched, A reads lane-private.

    // ---- stage 3: M2 = Z * V ; b := P = M2 + B0
    mm2(aE, b0, b1, acc0, acc1);
#pragma unroll
    for (int p = 0; p < 16; ++p) {
        const int i0 = 2 * p, i1 = 2 * p + 1;
        float m00, m01, m10, m11;
        upk2(m00, m01, acc0[p]); upk2(m10, m11, acc1[p]);
        b0[i0] = m00 + ldsf(Ac0 + (uint32_t)(i0 * ROWB));
        b0[i1] = m01 + ldsf(Ac0 + (uint32_t)(i1 * ROWB));
        b1[i0] = m10 + ldsf(Ac1 + (uint32_t)(i0 * ROWB));
        b1[i1] = m11 + ldsf(Ac1 + (uint32_t)(i1 * ROWB));
    }
    if (total > 4) {   // A := P (B0 dead); lane-private writes
#pragma unroll
        for (int i = 0; i < 32; ++i) {
            stsf(Ac0 + (uint32_t)(i * ROWB), b0[i]);
            stsf(Ac1 + (uint32_t)(i * ROWB), b1[i]);
        }
    }
    __syncwarp();   // P visible warp-wide

    // ---- squarings: P = P * P   (A-op = A, B-op = P regs)
    for (int s = 4; s < total; ++s) {
        mm2(aA, b0, b1, acc0, acc1);
#pragma unroll
        for (int p = 0; p < 16; ++p) {
            upk2(b0[2 * p], b0[2 * p + 1], acc0[p]);
            upk2(b1[2 * p], b1[2 * p + 1], acc1[p]);
        }
        __syncwarp();   // mm reads of A done before rewrite
        if (s < total - 1) {
#pragma unroll
            for (int i = 0; i < 32; ++i) {
                stsf(Ac0 + (uint32_t)(i * ROWB), b0[i]);
                stsf(Ac1 + (uint32_t)(i * ROWB), b1[i]);
            }
        }
        __syncwarp();
    }

    if (alive) {
        float* dst = out + (size_t)mat * 1024;
#pragma unroll
        for (int i = 0; i < 32; ++i) {
            dst[i * 32 + c0] = b0[i];
            dst[i * 32 + c1] = b1[i];
        }
    }
}

extern "C" void kernel_launch(void* const* d_in, const int* in_sizes, int n_in,
                              void* d_out, int out_size) {
    (void)n_in; (void)out_size;
    const float* x = (const float*)d_in[0];
    float* out = (float*)d_out;
    const int B = in_sizes[0] / 1024;
    const int ctas = (B + 1) / 2;
    ExpEig_52553219834314_kernel<<<ctas, 32>>>(x, out, B);
}

// round 9
// speedup vs baseline: 2.8413x; 2.8413x over previous
#include <cuda_runtime.h>
#include <cstdint>

// exp(X) for batched 32x32 symmetric fp32 via scaling-and-squaring, degree-8
// Paterson-Stockmeyer Taylor. TWO matrices per warp: half-warp h owns matrix h,
// lane (h,jj) owns columns jj and jj+16 of its matrix. A-operand rows come from
// smem (two distinct 16B rows per LDS.128, bank-disjoint via 16-word offset);
// B-operand columns live entirely in registers (previous stage's result).
// R9 = R2 verbatim + relaxed scaling radius theta=1.35 (one fewer squaring;
// accuracy validated at rel_err 2.2e-6 in R8).

#define STRIDE 36               // floats per smem row (conflict-free, 16B aligned)
#define MATF   1152             // floats per matrix buffer (32*36)
#define MOFF   1168             // matrix-1 offset inside a buffer: +16-word bank shift
#define BUFF   2320             // floats per buffer (2 matrices)

typedef unsigned long long u64;

__device__ __forceinline__ u64 pk2(float lo, float hi) {
    u64 r; asm("mov.b64 %0, {%1, %2};" : "=l"(r) : "f"(lo), "f"(hi)); return r;
}
__device__ __forceinline__ void upk2(float& lo, float& hi, u64 v) {
    asm("mov.b64 {%0, %1}, %2;" : "=f"(lo), "=f"(hi) : "l"(v));
}
__device__ __forceinline__ void fma2(u64& d, u64 a, u64 b) {
    asm("fma.rn.f32x2 %0, %1, %2, %0;" : "+l"(d) : "l"(a), "l"(b));
}

// C(:,c0|c1) = A * b, A rows from smem (my matrix), b columns in registers.
__device__ __forceinline__ void mm2(uint32_t aBase, const float* bc0, const float* bc1,
                                    u64 acc0[16], u64 acc1[16]) {
#pragma unroll
    for (int p = 0; p < 16; ++p) { acc0[p] = 0ULL; acc1[p] = 0ULL; }
#pragma unroll
    for (int k = 0; k < 32; ++k) {
        u64 bb0 = pk2(bc0[k], bc0[k]);
        u64 bb1 = pk2(bc1[k], bc1[k]);
        uint32_t ra = aBase + (uint32_t)(k * STRIDE * 4);
#pragma unroll
        for (int q = 0; q < 8; ++q) {
            u64 a0, a1;
            asm volatile("ld.shared.v2.u64 {%0, %1}, [%2];"
                         : "=l"(a0), "=l"(a1) : "r"(ra + (uint32_t)(q * 16)));
            fma2(acc0[2 * q],     a0, bb0);
            fma2(acc0[2 * q + 1], a1, bb0);
            fma2(acc1[2 * q],     a0, bb1);
            fma2(acc1[2 * q + 1], a1, bb1);
        }
    }
}

__global__ void __launch_bounds__(32)
ExpEig_52553219834314_kernel(const float* __restrict__ in,
                             float* __restrict__ out, int B) {
    __shared__ __align__(16) float smem[3 * BUFF];

    const int lane = threadIdx.x;
    const int h = lane >> 4, jj = lane & 15;
    int mat = blockIdx.x * 2 + h;
    const bool alive = (mat < B);
    if (!alive) mat = B - 1;
    const int c0 = jj, c1 = jj + 16;

    float* myA = smem + h * MOFF;          // Xs -> P (squaring chain)
    float* myB = myA + BUFF;               // X2s
    float* myD = myA + 2 * BUFF;           // B2 -> (M1+B1)
    const uint32_t aA = (uint32_t)__cvta_generic_to_shared(myA);
    const uint32_t aD = aA + (uint32_t)(2 * BUFF * 4);

    // Load X columns c0,c1 into regs; mirror full X into bufA (A-operand, stage 0).
    const float* src = in + (size_t)mat * 1024;
    float b0[32], b1[32];
#pragma unroll
    for (int i = 0; i < 32; ++i) { b0[i] = src[i * 32 + c0]; b1[i] = src[i * 32 + c1]; }
#pragma unroll
    for (int i = 0; i < 32; ++i) {
        myA[i * STRIDE + c0] = b0[i];
        myA[i * STRIDE + c1] = b1[i];
    }
    __syncwarp();

    u64 acc0[16], acc1[16];
    float c0v[32], c1v[32];

    // ---- stage 0: X2 = X * X  (A = X smem, B = X regs)
    mm2(aA, b0, b1, acc0, acc1);
#pragma unroll
    for (int p = 0; p < 16; ++p) {
        upk2(c0v[2 * p], c0v[2 * p + 1], acc0[p]);
        upk2(c1v[2 * p], c1v[2 * p + 1], acc1[p]);
    }
    __syncwarp();

    // Spectral bound per matrix: ||X||_2 <= sqrt(min(||X2||_1, ||X2||_F)).
    float sa = 0.f, sb = 0.f, fb = 0.f;
#pragma unroll
    for (int i = 0; i < 32; ++i) {
        sa += fabsf(c0v[i]); sb += fabsf(c1v[i]);
        fb += c0v[i] * c0v[i] + c1v[i] * c1v[i];
    }
    float rs = fmaxf(sa, sb);
#pragma unroll
    for (int off = 8; off > 0; off >>= 1) {   // reduce within half-warp (one matrix)
        rs = fmaxf(rs, __shfl_xor_sync(0xffffffffu, rs, off));
        fb += __shfl_xor_sync(0xffffffffu, fb, off);
    }
    float bnd = sqrtf(fminf(rs, sqrtf(fb)));
    bnd = fmaxf(bnd, __shfl_xor_sync(0xffffffffu, bnd, 16));  // uniform k across warp
    int e = 0; (void)frexpf(bnd * (1.f / 1.35f), &e);  // relaxed radius: ||Xs||<=1.35
    const int kk = e < 0 ? 0 : (e > 24 ? 24 : e);
    const int total = 4 + kk;
    const float s1 = exp2f(-(float)kk), s2 = s1 * s1;

    // Store Xs -> bufA, X2s -> bufB; bcol := X2s.
#pragma unroll
    for (int i = 0; i < 32; ++i) {
        myA[i * STRIDE + c0] = b0[i] * s1;
        myA[i * STRIDE + c1] = b1[i] * s1;
        float x20 = c0v[i] * s2, x21 = c1v[i] * s2;
        myB[i * STRIDE + c0] = x20;
        myB[i * STRIDE + c1] = x21;
        b0[i] = x20; b1[i] = x21;
    }
    __syncwarp();

    // ---- stage 1: Z = Xs * X2s  (A = Xs smem, B = X2s regs) -> Z stays in regs
    mm2(aA, b0, b1, acc0, acc1);
#pragma unroll
    for (int p = 0; p < 16; ++p) {           // unpack straight into bcol (Z)
        upk2(b0[2 * p], b0[2 * p + 1], acc0[p]);
        upk2(b1[2 * p], b1[2 * p + 1], acc1[p]);
    }
    __syncwarp();
    // Build B2 = I/720 + Xs/5040 + X2s/40320 -> bufD.
#pragma unroll
    for (int i = 0; i < 32; ++i) {
        float d0 = (i == c0) ? (1.f / 720.f) : 0.f;
        d0 += myA[i * STRIDE + c0] * (1.f / 5040.f);
        d0 += myB[i * STRIDE + c0] * (1.f / 40320.f);
        myD[i * STRIDE + c0] = d0;
        float d1 = (i == c1) ? (1.f / 720.f) : 0.f;
        d1 += myA[i * STRIDE + c1] * (1.f / 5040.f);
        d1 += myB[i * STRIDE + c1] * (1.f / 40320.f);
        myD[i * STRIDE + c1] = d1;
    }
    __syncwarp();

    // ---- stage 2: M1 = B2 * Z  (A = D smem, B = Z regs)
    mm2(aD, b0, b1, acc0, acc1);
#pragma unroll
    for (int p = 0; p < 16; ++p) {
        upk2(c0v[2 * p], c0v[2 * p + 1], acc0[p]);
        upk2(c1v[2 * p], c1v[2 * p + 1], acc1[p]);
    }
    __syncwarp();
    // D := M1 + B1, B1 = I/6 + Xs/24 + X2s/120.
#pragma unroll
    for (int i = 0; i < 32; ++i) {
        float v0 = c0v[i] + ((i == c0) ? (1.f / 6.f) : 0.f)
                 + myA[i * STRIDE + c0] * (1.f / 24.f)
                 + myB[i * STRIDE + c0] * (1.f / 120.f);
        float v1 = c1v[i] + ((i == c1) ? (1.f / 6.f) : 0.f)
                 + myA[i * STRIDE + c1] * (1.f / 24.f)
                 + myB[i * STRIDE + c1] * (1.f / 120.f);
        myD[i * STRIDE + c0] = v0;
        myD[i * STRIDE + c1] = v1;
    }
    __syncwarp();

    // ---- stage 3: M2 = (M1+B1) * Z ; P = M2 + I + Xs + X2s/2
    mm2(aD, b0, b1, acc0, acc1);
#pragma unroll
    for (int p = 0; p < 16; ++p) {           // result into bcol, then add B0 terms
        upk2(b0[2 * p], b0[2 * p + 1], acc0[p]);
        upk2(b1[2 * p], b1[2 * p + 1], acc1[p]);
    }
    __syncwarp();
#pragma unroll
    for (int i = 0; i < 32; ++i) {
        b0[i] += ((i == c0) ? 1.f : 0.f) + myA[i * STRIDE + c0]
               + myB[i * STRIDE + c0] * 0.5f;
        b1[i] += ((i == c1) ? 1.f : 0.f) + myA[i * STRIDE + c1]
               + myB[i * STRIDE + c1] * 0.5f;
    }
    __syncwarp();   // all Xs/X2s reads done before P overwrites bufA
    if (total > 4) {
#pragma unroll
        for (int i = 0; i < 32; ++i) {
            myA[i * STRIDE + c0] = b0[i];
            myA[i * STRIDE + c1] = b1[i];
        }
    }
    __syncwarp();

    // ---- squarings: P = P * P  (A = P smem, B = P regs)
    for (int s = 4; s < total; ++s) {
        mm2(aA, b0, b1, acc0, acc1);
#pragma unroll
        for (int p = 0; p < 16; ++p) {
            upk2(b0[2 * p], b0[2 * p + 1], acc0[p]);
            upk2(b1[2 * p], b1[2 * p + 1], acc1[p]);
        }
        __syncwarp();
        if (s < total - 1) {                 // last squaring: result goes to gmem only
#pragma unroll
            for (int i = 0; i < 32; ++i) {
                myA[i * STRIDE + c0] = b0[i];
                myA[i * STRIDE + c1] = b1[i];
            }
        }
        __syncwarp();
    }

    if (alive) {
        float* dst = out + (size_t)mat * 1024;
#pragma unroll
        for (int i = 0; i < 32; ++i) {
            dst[i * 32 + c0] = b0[i];
            dst[i * 32 + c1] = b1[i];
        }
    }
}

extern "C" void kernel_launch(void* const* d_in, const int* in_sizes, int n_in,
                              void* d_out, int out_size) {
    (void)n_in; (void)out_size;
    const float* x = (const float*)d_in[0];
    float* out = (float*)d_out;
    const int B = in_sizes[0] / 1024;
    const int ctas = (B + 1) / 2;
    ExpEig_52553219834314_kernel<<<ctas, 32>>>(x, out, B);
}